// round 10
// baseline (speedup 1.0000x reference)
#include <cuda_runtime.h>
#include <cuda_bf16.h>

// TripletLoss: loss = mean_t relu( ||a_t - p_t + eps||_2 - ||a_t - n_t + eps||_2 + margin )
// embeddings [N, 128] f32, triplet index arrays [T] int32. Output: 1 float.
// Fused, fence-free, ITERS=1 (one warp per triplet — best measured memory shape
// once the CCTL.IVALL fence confound is removed), __ldcg gathers (L1 bypass:
// hit prob ~1/148 on a 134MB table, and L1D is flushed per launch anyway).

#define MARGIN 0.5f
#define EPS 1e-6f
#define D 128
#define WARPS_PER_BLOCK 8
#define THREADS (WARPS_PER_BLOCK * 32)

__device__ float g_sum;             // zero at module load; last block resets
__device__ unsigned int g_ticket;   // zero at module load; last block resets

__device__ __forceinline__ unsigned int ticket_acq_rel(unsigned int* p) {
    unsigned int c;
    asm volatile("atom.add.acq_rel.gpu.global.u32 %0, [%1], 1;"
                 : "=r"(c) : "l"(p) : "memory");
    return c;
}

__device__ __forceinline__ float ld_acquire_f32(const float* p) {
    float v;
    asm volatile("ld.acquire.gpu.global.f32 %0, [%1];"
                 : "=f"(v) : "l"(p) : "memory");
    return v;
}

__global__ __launch_bounds__(THREADS) void triplet_kernel(
    const float* __restrict__ emb,
    const int* __restrict__ a_idx,
    const int* __restrict__ p_idx,
    const int* __restrict__ n_idx,
    int T,
    float* __restrict__ out)
{
    const int warp_in_block = threadIdx.x >> 5;
    const int lane = threadIdx.x & 31;
    const int t = blockIdx.x * WARPS_PER_BLOCK + warp_in_block;

    float acc = 0.0f;

    if (t < T) {
        const int ai = a_idx[t];
        const int pi = p_idx[t];
        const int ni = n_idx[t];

        // One float4 per lane per row; .cg = L2-only caching.
        float4 a4 = __ldcg((const float4*)(emb + (size_t)ai * D) + lane);
        float4 p4 = __ldcg((const float4*)(emb + (size_t)pi * D) + lane);
        float4 n4 = __ldcg((const float4*)(emb + (size_t)ni * D) + lane);

        float dp0 = a4.x - p4.x + EPS;
        float dp1 = a4.y - p4.y + EPS;
        float dp2 = a4.z - p4.z + EPS;
        float dp3 = a4.w - p4.w + EPS;
        float sp = dp0 * dp0 + dp1 * dp1 + dp2 * dp2 + dp3 * dp3;

        float dn0 = a4.x - n4.x + EPS;
        float dn1 = a4.y - n4.y + EPS;
        float dn2 = a4.z - n4.z + EPS;
        float dn3 = a4.w - n4.w + EPS;
        float sn = dn0 * dn0 + dn1 * dn1 + dn2 * dn2 + dn3 * dn3;

        // Fold halves, then split-warp: lanes 0-15 reduce sp, 16-31 reduce sn.
        sp += __shfl_xor_sync(0xFFFFFFFFu, sp, 16);
        sn += __shfl_xor_sync(0xFFFFFFFFu, sn, 16);
        float v = (lane < 16) ? sp : sn;
        #pragma unroll
        for (int off = 8; off > 0; off >>= 1)
            v += __shfl_xor_sync(0xFFFFFFFFu, v, off);

        float r = sqrtf(v);                                    // lane0: d_pos, lane16: d_neg
        float r_other = __shfl_xor_sync(0xFFFFFFFFu, r, 16);   // lane0 gets d_neg

        if (lane == 0) {
            float h = r - r_other + MARGIN;
            acc = (h > 0.0f) ? h : 0.0f;
        }
    }

    // ---- block reduction of lane-0 partials, one atomic per block ----
    __shared__ float warp_part[WARPS_PER_BLOCK];
    if (lane == 0) warp_part[warp_in_block] = acc;
    __syncthreads();

    __shared__ bool is_last;
    if (threadIdx.x == 0) {
        float s = 0.0f;
        #pragma unroll
        for (int w = 0; w < WARPS_PER_BLOCK; w++) s += warp_part[w];
        atomicAdd(&g_sum, s);                       // relaxed, L2-coherent
        unsigned int c = ticket_acq_rel(&g_ticket); // release: orders the add above
        is_last = (c == gridDim.x - 1);             // acquire: sees all prior adds
    }
    __syncthreads();

    // ---- last-block finalize (no fences, no extra kernels) ----
    if (is_last && threadIdx.x == 0) {
        float total = ld_acquire_f32(&g_sum);
        out[0] = total / (float)T;
        g_sum = 0.0f;     // reset for next graph replay (deterministic)
        g_ticket = 0;
    }
}

extern "C" void kernel_launch(void* const* d_in, const int* in_sizes, int n_in,
                              void* d_out, int out_size) {
    const float* emb   = (const float*)d_in[0];
    // d_in[1] = labels (unused; triplets already mined)
    const int* a_idx   = (const int*)d_in[2];
    const int* p_idx   = (const int*)d_in[3];
    const int* n_idx   = (const int*)d_in[4];
    float* out         = (float*)d_out;
    const int T        = in_sizes[2];

    int blocks = (T + WARPS_PER_BLOCK - 1) / WARPS_PER_BLOCK;  // 262144 -> 32768
    triplet_kernel<<<blocks, THREADS>>>(emb, a_idx, p_idx, n_idx, T, out);
}

// round 12
// speedup vs baseline: 2.7823x; 2.7823x over previous
#include <cuda_runtime.h>
#include <cuda_bf16.h>

// TripletLoss: loss = mean_t relu( ||a_t - p_t + eps||_2 - ||a_t - n_t + eps||_2 + margin )
// embeddings [N, 128] f32, triplet index arrays [T] int32. Output: 1 float.
// PERSISTENT fused kernel: grid = SMs*4 (one wave), each warp grid-strides over
// batches of 4 triplets with front-batched float4 gathers (R9's best memory
// shape), fence-free atomic finalize. Eliminates ~13 waves of CTA churn.

#define MARGIN 0.5f
#define EPS 1e-6f
#define D 128
#define WARPS_PER_BLOCK 8
#define THREADS (WARPS_PER_BLOCK * 32)
#define ITERS 4

__device__ float g_sum;             // zero at module load; last block resets
__device__ unsigned int g_ticket;   // zero at module load; last block resets

__device__ __forceinline__ unsigned int ticket_acq_rel(unsigned int* p) {
    unsigned int c;
    asm volatile("atom.add.acq_rel.gpu.global.u32 %0, [%1], 1;"
                 : "=r"(c) : "l"(p) : "memory");
    return c;
}

__device__ __forceinline__ float ld_acquire_f32(const float* p) {
    float v;
    asm volatile("ld.acquire.gpu.global.f32 %0, [%1];"
                 : "=f"(v) : "l"(p) : "memory");
    return v;
}

__global__ __launch_bounds__(THREADS) void triplet_kernel(
    const float* __restrict__ emb,
    const int* __restrict__ a_idx,
    const int* __restrict__ p_idx,
    const int* __restrict__ n_idx,
    int T,
    float* __restrict__ out)
{
    const int warp_in_block = threadIdx.x >> 5;
    const int lane = threadIdx.x & 31;
    const int warp_global = blockIdx.x * WARPS_PER_BLOCK + warp_in_block;
    const int n_warps = gridDim.x * WARPS_PER_BLOCK;
    const int stride = n_warps * ITERS;

    float acc = 0.0f;   // lane-0 accumulates hinge values across all batches

    for (int base = warp_global * ITERS; base < T; base += stride) {
        // ---- indices (uniform per warp, broadcast) ----
        int ai[ITERS], pi[ITERS], ni[ITERS];
        bool valid[ITERS];
        #pragma unroll
        for (int k = 0; k < ITERS; k++) {
            int t = base + k;
            valid[k] = (t < T);
            int tt = valid[k] ? t : 0;
            ai[k] = a_idx[tt];
            pi[k] = p_idx[tt];
            ni[k] = n_idx[tt];
        }

        // ---- front-batch all 12 row loads (one float4 per lane per row) ----
        float4 a4[ITERS], p4[ITERS], n4[ITERS];
        #pragma unroll
        for (int k = 0; k < ITERS; k++) {
            a4[k] = ((const float4*)(emb + (size_t)ai[k] * D))[lane];
            p4[k] = ((const float4*)(emb + (size_t)pi[k] * D))[lane];
            n4[k] = ((const float4*)(emb + (size_t)ni[k] * D))[lane];
        }

        // ---- per-triplet distance + hinge ----
        #pragma unroll
        for (int k = 0; k < ITERS; k++) {
            float dp0 = a4[k].x - p4[k].x + EPS;
            float dp1 = a4[k].y - p4[k].y + EPS;
            float dp2 = a4[k].z - p4[k].z + EPS;
            float dp3 = a4[k].w - p4[k].w + EPS;
            float sp = dp0 * dp0 + dp1 * dp1 + dp2 * dp2 + dp3 * dp3;

            float dn0 = a4[k].x - n4[k].x + EPS;
            float dn1 = a4[k].y - n4[k].y + EPS;
            float dn2 = a4[k].z - n4[k].z + EPS;
            float dn3 = a4[k].w - n4[k].w + EPS;
            float sn = dn0 * dn0 + dn1 * dn1 + dn2 * dn2 + dn3 * dn3;

            // Fold halves, then split-warp: lanes 0-15 reduce sp, 16-31 reduce sn.
            sp += __shfl_xor_sync(0xFFFFFFFFu, sp, 16);
            sn += __shfl_xor_sync(0xFFFFFFFFu, sn, 16);
            float v = (lane < 16) ? sp : sn;
            #pragma unroll
            for (int off = 8; off > 0; off >>= 1)
                v += __shfl_xor_sync(0xFFFFFFFFu, v, off);

            float r = sqrtf(v);                                  // lane0: d_pos, lane16: d_neg
            float r_other = __shfl_xor_sync(0xFFFFFFFFu, r, 16); // lane0 gets d_neg

            if (lane == 0 && valid[k]) {
                float h = r - r_other + MARGIN;
                acc += (h > 0.0f) ? h : 0.0f;
            }
        }
    }

    // ---- block reduction of lane-0 partials, one atomic per block ----
    __shared__ float warp_part[WARPS_PER_BLOCK];
    if (lane == 0) warp_part[warp_in_block] = acc;
    __syncthreads();

    __shared__ bool is_last;
    if (threadIdx.x == 0) {
        float s = 0.0f;
        #pragma unroll
        for (int w = 0; w < WARPS_PER_BLOCK; w++) s += warp_part[w];
        atomicAdd(&g_sum, s);                       // relaxed, L2-coherent
        unsigned int c = ticket_acq_rel(&g_ticket); // release: orders the add above
        is_last = (c == gridDim.x - 1);             // acquire: sees all prior adds
    }
    __syncthreads();

    // ---- last-block finalize (no fences, no extra kernels) ----
    if (is_last && threadIdx.x == 0) {
        float total = ld_acquire_f32(&g_sum);
        out[0] = total / (float)T;
        g_sum = 0.0f;     // reset for next graph replay (deterministic)
        g_ticket = 0;
    }
}

extern "C" void kernel_launch(void* const* d_in, const int* in_sizes, int n_in,
                              void* d_out, int out_size) {
    const float* emb   = (const float*)d_in[0];
    // d_in[1] = labels (unused; triplets already mined)
    const int* a_idx   = (const int*)d_in[2];
    const int* p_idx   = (const int*)d_in[3];
    const int* n_idx   = (const int*)d_in[4];
    float* out         = (float*)d_out;
    const int T        = in_sizes[2];

    // Persistent one-wave grid: 4 CTAs/SM (regs ~56 -> occupancy limit 4).
    static int num_sms = 0;
    if (num_sms == 0) {
        cudaDeviceGetAttribute(&num_sms, cudaDevAttrMultiProcessorCount, 0);
        if (num_sms <= 0) num_sms = 148;
    }
    int blocks = num_sms * 4;   // GB300: 152*4 = 608

    triplet_kernel<<<blocks, THREADS>>>(emb, a_idx, p_idx, n_idx, T, out);
}